// round 14
// baseline (speedup 1.0000x reference)
#include <cuda_runtime.h>
#include <cuda_fp16.h>
#include <math.h>
#include <stdint.h>

#define BATCHN  16
#define SEQL    2048
#define INDIM   64
#define HID     256
#define STATEN  256
#define MLPD    1024
#define OUTD    128
#define NLAYERS 4
#define M_TOT   (BATCHN*SEQL)   /* 32768 */
#define CH      16
#define NCH     (SEQL/CH)       /* 128 */
#define LOG2CH  4
#define SGRP    8               /* states per scan block */
#define S2      (2*STATEN)      /* 512 */

// ---------------- scratch (static device globals) ---------------------------
__device__ __half g_h [M_TOT*HID];
__device__ __half g_y [M_TOT*HID];
__device__ __half g_bu[M_TOT*S2];        // interleaved: col 2s = re_s, 2s+1 = im_s (fp16)
__device__ __half g_st[M_TOT*S2];        // interleaved likewise
__device__ __half g_z [M_TOT*MLPD];
__device__ __half g_xr  [M_TOT*INDIM];
__device__ __half g_wE  [HID*INDIM];
__device__ __half g_wB  [NLAYERS*S2*HID];   // row 2s=Bre[s]*ga, 2s+1=Bim[s]*ga
__device__ __half g_wC  [NLAYERS*HID*S2];   // col 2s=Cre[.][s], 2s+1=-Cim[.][s]
__device__ __half g_wH  [NLAYERS*MLPD*HID];
__device__ __half g_wO  [NLAYERS*HID*MLPD];
__device__ __half g_wOut[OUTD*HID];

// ==================== FP16 tensor-core GEMM =================================
// C[M,N] = epi(A[M,K] @ W[N,K]^T); A,W fp16; accumulate fp32.
// epi: 0 raw | 1 +bias | 2 gelu(+bias) | 3 +bias+resid | 7 + bias[c]*resid
#define BM   128
#define BK   32            /* k elements per stage */
#define HSTR 40            /* padded row stride in halves (80B) — ldmatrix conflict-free */
#define NSTG 5

__device__ __forceinline__ void cp16(uint32_t dst, const void* src){
    asm volatile("cp.async.ca.shared.global [%0], [%1], 16;\n" :: "r"(dst), "l"(src));
}
__device__ __forceinline__ void mma_f16(float* c, const uint32_t* a, const uint32_t* b){
    asm volatile("mma.sync.aligned.m16n8k16.row.col.f32.f16.f16.f32 "
        "{%0,%1,%2,%3}, {%4,%5,%6,%7}, {%8,%9}, {%0,%1,%2,%3};"
        : "+f"(c[0]), "+f"(c[1]), "+f"(c[2]), "+f"(c[3])
        : "r"(a[0]), "r"(a[1]), "r"(a[2]), "r"(a[3]), "r"(b[0]), "r"(b[1]));
}
__device__ __forceinline__ void ldm4(uint32_t& r0, uint32_t& r1, uint32_t& r2, uint32_t& r3,
                                     uint32_t addr){
    asm volatile("ldmatrix.sync.aligned.m8n8.x4.shared.b16 {%0,%1,%2,%3}, [%4];"
        : "=r"(r0), "=r"(r1), "=r"(r2), "=r"(r3) : "r"(addr));
}

template<typename CT>
__device__ __forceinline__ void store2(CT* C, size_t off, float v0, float v1);
template<> __device__ __forceinline__ void store2<__half>(__half* C, size_t off, float v0, float v1){
    *(__half2*)(C + off) = __floats2half2_rn(v0, v1);
}
template<> __device__ __forceinline__ void store2<float>(float* C, size_t off, float v0, float v1){
    C[off] = v0; C[off+1] = v1;
}
template<typename CT>
__device__ __forceinline__ float rd(const CT* p, size_t off);
template<> __device__ __forceinline__ float rd<__half>(const __half* p, size_t off){ return __half2float(p[off]); }
template<> __device__ __forceinline__ float rd<float>(const float* p, size_t off){ return p[off]; }

template<int BN, typename CT>
__global__ __launch_bounds__(256, 2)
void gemm_h(int M, int N, int K,
            const __half* __restrict__ A, const __half* __restrict__ W,
            const float* __restrict__ bias, const CT* __restrict__ resid,
            CT* __restrict__ C, int epi)
{
    constexpr int NT    = BN/32;                 // n fragments per warp (4)
    constexpr int NP    = NT/2;
    constexpr int NLB   = BN/64;
    constexpr int SLOTA = BM*HSTR;               // halves
    constexpr int SLOTB = BN*HSTR;

    extern __shared__ __align__(16) __half smem[];
    __half* As = smem;
    __half* Bs = smem + NSTG*SLOTA;

    int tid  = threadIdx.x;
    int lane = tid & 31;
    int wid  = tid >> 5;
    int gr   = lane >> 2;
    int ct   = lane & 3;
    int wm   = (wid >> 2) * 64;
    int wn   = (wid & 3) * (BN/4);
    int row0 = blockIdx.y * BM;
    int col0 = blockIdx.x * BN;

    uint32_t sAb = (uint32_t)__cvta_generic_to_shared(As);
    uint32_t sBb = (uint32_t)__cvta_generic_to_shared(Bs);

    // ldmatrix per-lane base addresses (within stage 0)
    uint32_t aBase = sAb + (uint32_t)((wm + ((lane>>3)&1)*8 + (lane&7))*HSTR)*2
                   + (uint32_t)(lane>>4)*16;
    uint32_t bBase = sBb + (uint32_t)((wn + (lane>>4)*8 + (lane&7))*HSTR)*2
                   + (uint32_t)((lane>>3)&1)*16;

    float acc[4][NT][4];
    #pragma unroll
    for (int i=0;i<4;i++)
        #pragma unroll
        for (int j=0;j<NT;j++)
            #pragma unroll
            for (int q=0;q<4;q++) acc[i][j][q] = 0.f;

    int nk = K / BK;   // always even for our shapes

    // guarded stage load: only touches memory when kt < nk; ALWAYS commits a
    // group so wait_group accounting stays consistent.
    auto load_stage = [&](int kt){
        if (kt < nk) {
            int slot = kt % NSTG;
            int k0 = kt * BK;
            #pragma unroll
            for (int j = 0; j < 2; j++) {
                int id = tid + j*256;
                int r = id >> 2, kb = id & 3;
                cp16(sAb + (slot*SLOTA + r*HSTR)*2 + kb*16,
                     A + (size_t)(row0 + r)*K + k0 + kb*8);
            }
            #pragma unroll
            for (int j = 0; j < NLB; j++) {
                int id = tid + j*256;
                int r = id >> 2, kb = id & 3;
                cp16(sBb + (slot*SLOTB + r*HSTR)*2 + kb*16,
                     W + (size_t)(col0 + r)*K + k0 + kb*8);
            }
        }
        asm volatile("cp.async.commit_group;\n");
    };

    auto compute_tile = [&](int kt){
        int slot = kt % NSTG;
        uint32_t aSlot = aBase + slot*SLOTA*2;
        uint32_t bSlot = bBase + slot*SLOTB*2;
        #pragma unroll
        for (int ks = 0; ks < 2; ks++) {     // two k16 steps per stage
            uint32_t ua[4][4], ub[NT][2];
            #pragma unroll
            for (int mt = 0; mt < 4; mt++)
                ldm4(ua[mt][0], ua[mt][1], ua[mt][2], ua[mt][3],
                     aSlot + mt*16*HSTR*2 + ks*32);
            #pragma unroll
            for (int p = 0; p < NP; p++)
                ldm4(ub[2*p][0], ub[2*p][1], ub[2*p+1][0], ub[2*p+1][1],
                     bSlot + p*16*HSTR*2 + ks*32);
            #pragma unroll
            for (int mt = 0; mt < 4; mt++)
                #pragma unroll
                for (int nt = 0; nt < NT; nt++)
                    mma_f16(acc[mt][nt], ua[mt], ub[nt]);
        }
    };

    // prologue: 3 stages in flight
    load_stage(0);
    load_stage(1);
    load_stage(2);

    // mainloop: two k-tiles per barrier
    for (int kt = 0; kt < nk; kt += 2) {
        asm volatile("cp.async.wait_group 1;\n");   // groups kt, kt+1 complete
        __syncthreads();
        load_stage(kt + 3);     // slot (kt+3)%5 — freed two iterations ago
        load_stage(kt + 4);     // slot (kt+4)%5 — freed last iteration
        compute_tile(kt);
        compute_tile(kt + 1);
    }

    #pragma unroll
    for (int mt = 0; mt < 4; mt++) {
        #pragma unroll
        for (int half = 0; half < 2; half++) {
            int r = row0 + wm + mt*16 + gr + half*8;
            size_t ro = (size_t)r * N;
            #pragma unroll
            for (int nt = 0; nt < NT; nt++) {
                int cc = col0 + wn + nt*8 + ct*2;
                float v0 = acc[mt][nt][half*2 + 0];
                float v1 = acc[mt][nt][half*2 + 1];
                if (epi == 1) {
                    v0 += bias[cc]; v1 += bias[cc+1];
                } else if (epi == 2) {
                    float t0 = v0 + bias[cc], t1 = v1 + bias[cc+1];
                    v0 = 0.5f * t0 * (1.0f + erff(t0 * 0.70710678118654752f));
                    v1 = 0.5f * t1 * (1.0f + erff(t1 * 0.70710678118654752f));
                } else if (epi == 3) {
                    v0 += bias[cc]   + rd<CT>(resid, ro+cc);
                    v1 += bias[cc+1] + rd<CT>(resid, ro+cc+1);
                } else if (epi == 7) {
                    v0 += bias[cc]   * rd<CT>(resid, ro+cc);
                    v1 += bias[cc+1] * rd<CT>(resid, ro+cc+1);
                }
                store2<CT>(C, ro + cc, v0, v1);
            }
        }
    }
}

// ==================== unified prep kernel ===================================
__global__ void prep_all(const float* __restrict__ x,    const float* __restrict__ embW,
                         const float* __restrict__ outW, const float* __restrict__ Wh,
                         const float* __restrict__ Wo,   const float* __restrict__ Bre,
                         const float* __restrict__ Bim,  const float* __restrict__ Cre,
                         const float* __restrict__ Cim,  const float* __restrict__ gl)
{
    const int N0 = M_TOT*INDIM/4;
    const int N1 = N0 + HID*INDIM/4;
    const int N2 = N1 + OUTD*HID/4;
    const int N3 = N2 + NLAYERS*MLPD*HID/4;
    const int N4 = N3 + NLAYERS*HID*MLPD/4;
    const int N5 = N4 + NLAYERS*S2*HID;
    const int N6 = N5 + NLAYERS*HID*S2;

    int i = blockIdx.x * blockDim.x + threadIdx.x;
    if (i < N4) {
        const float* src; __half* dst; int j;
        if (i < N0)      { src = x;    dst = g_xr;   j = i; }
        else if (i < N1) { src = embW; dst = g_wE;   j = i - N0; }
        else if (i < N2) { src = outW; dst = g_wOut; j = i - N1; }
        else if (i < N3) { src = Wh;   dst = g_wH;   j = i - N2; }
        else             { src = Wo;   dst = g_wO;   j = i - N3; }
        float4 v = ((const float4*)src)[j];
        ((__half2*)dst)[j*2]   = __floats2half2_rn(v.x, v.y);
        ((__half2*)dst)[j*2+1] = __floats2half2_rn(v.z, v.w);
    } else if (i < N5) {
        int j  = i - N4;
        int k  = j & (HID-1);
        int rr = (j >> 8) & (S2-1);
        int l  = j >> 17;
        int s  = rr >> 1;
        float ga = expf(gl[l*STATEN + s]);
        float v = (rr & 1) ? Bim[((size_t)l*STATEN + s)*HID + k]
                           : Bre[((size_t)l*STATEN + s)*HID + k];
        g_wB[j] = __float2half_rn(v * ga);
    } else if (i < N6) {
        int j  = i - N5;
        int kk = j & (S2-1);
        int hh = (j >> 9) & (HID-1);
        int l  = j >> 17;
        int s  = kk >> 1;
        float v = (kk & 1) ? -Cim[((size_t)l*HID + hh)*STATEN + s]
                           :  Cre[((size_t)l*HID + hh)*STATEN + s];
        g_wC[j] = __float2half_rn(v);
    }
}
#define PREP_TOTAL (M_TOT*INDIM/4 + HID*INDIM/4 + OUTD*HID/4 + NLAYERS*MLPD*HID/4 \
                    + NLAYERS*HID*MLPD/4 + NLAYERS*S2*HID + NLAYERS*HID*S2)

// ==================== fused LRU scan ========================================
__device__ __forceinline__ void lam_of(const float* nu_log, const float* th_log,
                                       int layer, int s, float& lre, float& lim)
{
    float nu = nu_log[layer*STATEN + s];
    float th = th_log[layer*STATEN + s];
    float mag = expf(-expf(nu));
    float ang = expf(th);
    float sv, cv;
    sincosf(ang, &sv, &cv);
    lre = mag * cv;
    lim = mag * sv;
}

// grid: (STATEN/SGRP, BATCHN) = (32,16), block: 1024 = 128 chunks x 8 states
// (gamma already folded into wB; bu is fp16 interleaved)
__global__ __launch_bounds__(1024)
void scan_fused(const float* __restrict__ nu_log, const float* __restrict__ th_log,
                int layer)
{
    __shared__ float se_r[NCH][SGRP], se_i[NCH][SGRP];
    __shared__ float ca_r[NCH][SGRP], ca_i[NCH][SGRP];

    int tid = threadIdx.x;
    int c   = tid >> 3;            // chunk 0..127
    int sl  = tid & (SGRP-1);      // state lane 0..7
    int s   = blockIdx.x * SGRP + sl;
    int b   = blockIdx.y;

    float lre, lim;
    lam_of(nu_log, th_log, layer, s, lre, lim);

    size_t base2 = ((size_t)b * SEQL + (size_t)c * CH) * STATEN + s;
    const __half2* bu2 = (const __half2*)g_bu;
    __half2*       st2 = (__half2*)g_st;

    // phase 1: local scan, keep chunk-end state
    {
        float sr = 0.f, si = 0.f;
        #pragma unroll
        for (int t = 0; t < CH; t++) {
            float2 u = __half22float2(bu2[base2 + (size_t)t * STATEN]);
            float nr = fmaf(lre, sr, fmaf(-lim, si, u.x));
            float ni = fmaf(lre, si, fmaf( lim, sr, u.y));
            sr = nr; si = ni;
        }
        se_r[c][sl] = sr; se_i[c][sl] = si;
    }
    __syncthreads();

    // phase 2: serial carry combine (first SGRP threads; for them sl == tid)
    if (tid < SGRP) {
        float ar = lre, ai = lim;     // lam^CH via LOG2CH squarings
        #pragma unroll
        for (int q = 0; q < LOG2CH; q++) {
            float nr = ar*ar - ai*ai;
            ai = 2.f * ar * ai;
            ar = nr;
        }
        float cr = 0.f, ci = 0.f;
        #pragma unroll 8
        for (int c2 = 0; c2 < NCH; c2++) {
            ca_r[c2][sl] = cr; ca_i[c2][sl] = ci;
            float er = se_r[c2][sl], ei = se_i[c2][sl];
            float nr = fmaf(ar, cr, fmaf(-ai, ci, er));
            float ni = fmaf(ar, ci, fmaf( ai, cr, ei));
            cr = nr; ci = ni;
        }
    }
    __syncthreads();

    // phase 3: rescan with carry-in, write fp16 states
    {
        float sr = ca_r[c][sl], si = ca_i[c][sl];
        #pragma unroll
        for (int t = 0; t < CH; t++) {
            float2 u = __half22float2(bu2[base2 + (size_t)t * STATEN]);
            float nr = fmaf(lre, sr, fmaf(-lim, si, u.x));
            float ni = fmaf(lre, si, fmaf( lim, sr, u.y));
            sr = nr; si = ni;
            st2[base2 + (size_t)t * STATEN] = __floats2half2_rn(sr, si);
        }
    }
}

// ==================== driver ================================================
extern "C" void kernel_launch(void* const* d_in, const int* in_sizes, int n_in,
                              void* d_out, int out_size)
{
    (void)in_sizes; (void)n_in; (void)out_size;
    const float* x    = (const float*)d_in[0];
    const float* embW = (const float*)d_in[1];
    const float* embb = (const float*)d_in[2];
    const float* nu   = (const float*)d_in[3];
    const float* th   = (const float*)d_in[4];
    const float* gl   = (const float*)d_in[5];
    const float* Bre  = (const float*)d_in[6];
    const float* Bim  = (const float*)d_in[7];
    const float* Cre  = (const float*)d_in[8];
    const float* Cim  = (const float*)d_in[9];
    const float* Dv   = (const float*)d_in[10];
    const float* Wh   = (const float*)d_in[11];
    const float* bh   = (const float*)d_in[12];
    const float* Wo   = (const float*)d_in[13];
    const float* bo   = (const float*)d_in[14];
    const float* outW = (const float*)d_in[15];
    const float* outb = (const float*)d_in[16];
    float* out = (float*)d_out;

    __half *h, *y, *z, *xr, *wE, *wB, *wC, *wH, *wO, *wOut, *stp, *bup;
    cudaGetSymbolAddress((void**)&h,    g_h);
    cudaGetSymbolAddress((void**)&y,    g_y);
    cudaGetSymbolAddress((void**)&z,    g_z);
    cudaGetSymbolAddress((void**)&xr,   g_xr);
    cudaGetSymbolAddress((void**)&wE,   g_wE);
    cudaGetSymbolAddress((void**)&wB,   g_wB);
    cudaGetSymbolAddress((void**)&wC,   g_wC);
    cudaGetSymbolAddress((void**)&wH,   g_wH);
    cudaGetSymbolAddress((void**)&wO,   g_wO);
    cudaGetSymbolAddress((void**)&wOut, g_wOut);
    cudaGetSymbolAddress((void**)&stp,  g_st);
    cudaGetSymbolAddress((void**)&bup,  g_bu);

    const int SM128 = NSTG*(BM+128)*HSTR*2;   // 102400
    cudaFuncSetAttribute((const void*)gemm_h<128,__half>, cudaFuncAttributeMaxDynamicSharedMemorySize, SM128);
    cudaFuncSetAttribute((const void*)gemm_h<128,float>,  cudaFuncAttributeMaxDynamicSharedMemorySize, SM128);

    dim3 tb(256);
    const int MB = M_TOT / BM;   // 256

    // ---- prep: ONE kernel for all conversions/concats (gamma folded) ----
    prep_all<<<(PREP_TOTAL + 255)/256, tb>>>(x, embW, outW, Wh, Wo, Bre, Bim, Cre, Cim, gl);

    // embedding: h = half(x @ embW^T + embb)
    gemm_h<128,__half><<<dim3(HID/128, MB), tb, SM128>>>(M_TOT, HID, INDIM, xr, wE, embb, (const __half*)nullptr, h, 1);

    for (int l = 0; l < NLAYERS; l++) {
        // bu = h @ Bcat^T   [M, 512] fp16 (gamma pre-applied)
        gemm_h<128,__half><<<dim3(S2/128, MB), tb, SM128>>>(M_TOT, S2, HID, h, wB + (size_t)l*S2*HID,
                                                            (const float*)nullptr, (const __half*)nullptr, bup, 0);
        // fused chunked complex scan
        scan_fused<<<dim3(STATEN/SGRP, BATCHN), 1024>>>(nu, th, l);

        // y = half([st interleaved] @ wC^T + D*h)
        gemm_h<128,__half><<<dim3(HID/128, MB), tb, SM128>>>(M_TOT, HID, S2, stp, wC + (size_t)l*HID*S2,
                                                             Dv + (size_t)l*HID, h, y, 7);
        // MLP
        gemm_h<128,__half><<<dim3(MLPD/128, MB), tb, SM128>>>(M_TOT, MLPD, HID, y, wH + (size_t)l*MLPD*HID,
                                                              bh + (size_t)l*MLPD, (const __half*)nullptr, z, 2);
        gemm_h<128,__half><<<dim3(HID/128, MB), tb, SM128>>>(M_TOT, HID, MLPD, z, wO + (size_t)l*HID*MLPD,
                                                             bo + (size_t)l*HID, y, h, 3);
    }

    // out = h @ outW^T + outb   (fp32 store)
    gemm_h<128,float><<<dim3(OUTD/128, MB), tb, SM128>>>(M_TOT, OUTD, HID, h, wOut, outb, (const float*)nullptr, out, 1);
}

// round 15
// speedup vs baseline: 1.0787x; 1.0787x over previous
#include <cuda_runtime.h>
#include <cuda_fp16.h>
#include <math.h>
#include <stdint.h>

#define BATCHN  16
#define SEQL    2048
#define INDIM   64
#define HID     256
#define STATEN  256
#define MLPD    1024
#define OUTD    128
#define NLAYERS 4
#define M_TOT   (BATCHN*SEQL)   /* 32768 */
#define CH      32
#define NCH     (SEQL/CH)       /* 64 */
#define LOG2CH  5
#define SGRP    8               /* states per scan block */
#define S2      (2*STATEN)      /* 512 */

// ---------------- scratch (static device globals) ---------------------------
__device__ __half g_h [M_TOT*HID];
__device__ __half g_y [M_TOT*HID];
__device__ __half g_bu[M_TOT*S2];        // interleaved: col 2s = re_s, 2s+1 = im_s (fp16)
__device__ __half g_st[M_TOT*S2];        // interleaved likewise
__device__ __half g_z [M_TOT*MLPD];
__device__ __half g_xr  [M_TOT*INDIM];
__device__ __half g_wE  [HID*INDIM];
__device__ __half g_wB  [NLAYERS*S2*HID];   // row 2s=Bre[s]*ga, 2s+1=Bim[s]*ga
__device__ __half g_wC  [NLAYERS*HID*S2];   // col 2s=Cre[.][s], 2s+1=-Cim[.][s]
__device__ __half g_wH  [NLAYERS*MLPD*HID];
__device__ __half g_wO  [NLAYERS*HID*MLPD];
__device__ __half g_wOut[OUTD*HID];

// ==================== FP16 tensor-core GEMM (R13-proven) ====================
// C[M,N] = epi(A[M,K] @ W[N,K]^T); A,W fp16; accumulate fp32.
// epi: 0 raw | 1 +bias | 2 gelu(+bias) | 3 +bias+resid | 7 + bias[c]*resid
#define BM   128
#define BK   32            /* k elements per stage */
#define HSTR 40            /* padded row stride in halves (80B) — ldmatrix conflict-free */
#define NSTG 4

__device__ __forceinline__ void cp16(uint32_t dst, const void* src){
    asm volatile("cp.async.ca.shared.global [%0], [%1], 16;\n" :: "r"(dst), "l"(src));
}
__device__ __forceinline__ void mma_f16(float* c, const uint32_t* a, const uint32_t* b){
    asm volatile("mma.sync.aligned.m16n8k16.row.col.f32.f16.f16.f32 "
        "{%0,%1,%2,%3}, {%4,%5,%6,%7}, {%8,%9}, {%0,%1,%2,%3};"
        : "+f"(c[0]), "+f"(c[1]), "+f"(c[2]), "+f"(c[3])
        : "r"(a[0]), "r"(a[1]), "r"(a[2]), "r"(a[3]), "r"(b[0]), "r"(b[1]));
}
__device__ __forceinline__ void ldm4(uint32_t& r0, uint32_t& r1, uint32_t& r2, uint32_t& r3,
                                     uint32_t addr){
    asm volatile("ldmatrix.sync.aligned.m8n8.x4.shared.b16 {%0,%1,%2,%3}, [%4];"
        : "=r"(r0), "=r"(r1), "=r"(r2), "=r"(r3) : "r"(addr));
}

template<typename CT>
__device__ __forceinline__ void store2(CT* C, size_t off, float v0, float v1);
template<> __device__ __forceinline__ void store2<__half>(__half* C, size_t off, float v0, float v1){
    *(__half2*)(C + off) = __floats2half2_rn(v0, v1);
}
template<> __device__ __forceinline__ void store2<float>(float* C, size_t off, float v0, float v1){
    C[off] = v0; C[off+1] = v1;
}
template<typename CT>
__device__ __forceinline__ float rd(const CT* p, size_t off);
template<> __device__ __forceinline__ float rd<__half>(const __half* p, size_t off){ return __half2float(p[off]); }
template<> __device__ __forceinline__ float rd<float>(const float* p, size_t off){ return p[off]; }

template<int BN, typename CT>
__global__ __launch_bounds__(256, 2)
void gemm_h(int M, int N, int K,
            const __half* __restrict__ A, const __half* __restrict__ W,
            const float* __restrict__ bias, const CT* __restrict__ resid,
            CT* __restrict__ C, int epi)
{
    constexpr int NT    = BN/32;                 // n fragments per warp (4)
    constexpr int NP    = NT/2;
    constexpr int NLB   = BN/64;
    constexpr int SLOTA = BM*HSTR;               // halves
    constexpr int SLOTB = BN*HSTR;

    extern __shared__ __align__(16) __half smem[];
    __half* As = smem;
    __half* Bs = smem + NSTG*SLOTA;

    int tid  = threadIdx.x;
    int lane = tid & 31;
    int wid  = tid >> 5;
    int gr   = lane >> 2;
    int ct   = lane & 3;
    int wm   = (wid >> 2) * 64;
    int wn   = (wid & 3) * (BN/4);
    int row0 = blockIdx.y * BM;
    int col0 = blockIdx.x * BN;

    uint32_t sAb = (uint32_t)__cvta_generic_to_shared(As);
    uint32_t sBb = (uint32_t)__cvta_generic_to_shared(Bs);

    // ldmatrix per-lane base addresses (within stage 0)
    uint32_t aBase = sAb + (uint32_t)((wm + ((lane>>3)&1)*8 + (lane&7))*HSTR)*2
                   + (uint32_t)(lane>>4)*16;
    uint32_t bBase = sBb + (uint32_t)((wn + (lane>>4)*8 + (lane&7))*HSTR)*2
                   + (uint32_t)((lane>>3)&1)*16;

    float acc[4][NT][4];
    #pragma unroll
    for (int i=0;i<4;i++)
        #pragma unroll
        for (int j=0;j<NT;j++)
            #pragma unroll
            for (int q=0;q<4;q++) acc[i][j][q] = 0.f;

    int nk = K / BK;

    // guarded stage load: only touches memory when kt < nk; ALWAYS commits a
    // group so wait_group accounting stays consistent.
    auto load_stage = [&](int kt){
        if (kt < nk) {
            int slot = kt % NSTG;
            int k0 = kt * BK;
            #pragma unroll
            for (int j = 0; j < 2; j++) {
                int id = tid + j*256;
                int r = id >> 2, kb = id & 3;
                cp16(sAb + (slot*SLOTA + r*HSTR)*2 + kb*16,
                     A + (size_t)(row0 + r)*K + k0 + kb*8);
            }
            #pragma unroll
            for (int j = 0; j < NLB; j++) {
                int id = tid + j*256;
                int r = id >> 2, kb = id & 3;
                cp16(sBb + (slot*SLOTB + r*HSTR)*2 + kb*16,
                     W + (size_t)(col0 + r)*K + k0 + kb*8);
            }
        }
        asm volatile("cp.async.commit_group;\n");
    };

    load_stage(0);
    load_stage(1);
    load_stage(2);

    for (int kt = 0; kt < nk; kt++) {
        asm volatile("cp.async.wait_group 2;\n");
        __syncthreads();
        load_stage(kt + 3);

        int slot = kt % NSTG;
        uint32_t aSlot = aBase + slot*SLOTA*2;
        uint32_t bSlot = bBase + slot*SLOTB*2;
        #pragma unroll
        for (int ks = 0; ks < 2; ks++) {     // two k16 steps per stage
            uint32_t ua[4][4], ub[NT][2];
            #pragma unroll
            for (int mt = 0; mt < 4; mt++)
                ldm4(ua[mt][0], ua[mt][1], ua[mt][2], ua[mt][3],
                     aSlot + mt*16*HSTR*2 + ks*32);
            #pragma unroll
            for (int p = 0; p < NP; p++)
                ldm4(ub[2*p][0], ub[2*p][1], ub[2*p+1][0], ub[2*p+1][1],
                     bSlot + p*16*HSTR*2 + ks*32);
            #pragma unroll
            for (int mt = 0; mt < 4; mt++)
                #pragma unroll
                for (int nt = 0; nt < NT; nt++)
                    mma_f16(acc[mt][nt], ua[mt], ub[nt]);
        }
    }

    #pragma unroll
    for (int mt = 0; mt < 4; mt++) {
        #pragma unroll
        for (int half = 0; half < 2; half++) {
            int r = row0 + wm + mt*16 + gr + half*8;
            size_t ro = (size_t)r * N;
            #pragma unroll
            for (int nt = 0; nt < NT; nt++) {
                int cc = col0 + wn + nt*8 + ct*2;
                float v0 = acc[mt][nt][half*2 + 0];
                float v1 = acc[mt][nt][half*2 + 1];
                if (epi == 1) {
                    v0 += bias[cc]; v1 += bias[cc+1];
                } else if (epi == 2) {
                    float t0 = v0 + bias[cc], t1 = v1 + bias[cc+1];
                    v0 = 0.5f * t0 * (1.0f + erff(t0 * 0.70710678118654752f));
                    v1 = 0.5f * t1 * (1.0f + erff(t1 * 0.70710678118654752f));
                } else if (epi == 3) {
                    v0 += bias[cc]   + rd<CT>(resid, ro+cc);
                    v1 += bias[cc+1] + rd<CT>(resid, ro+cc+1);
                } else if (epi == 7) {
                    v0 += bias[cc]   * rd<CT>(resid, ro+cc);
                    v1 += bias[cc+1] * rd<CT>(resid, ro+cc+1);
                }
                store2<CT>(C, ro + cc, v0, v1);
            }
        }
    }
}

// ==================== unified prep kernel ===================================
__global__ void prep_all(const float* __restrict__ x,    const float* __restrict__ embW,
                         const float* __restrict__ outW, const float* __restrict__ Wh,
                         const float* __restrict__ Wo,   const float* __restrict__ Bre,
                         const float* __restrict__ Bim,  const float* __restrict__ Cre,
                         const float* __restrict__ Cim,  const float* __restrict__ gl)
{
    const int N0 = M_TOT*INDIM/4;
    const int N1 = N0 + HID*INDIM/4;
    const int N2 = N1 + OUTD*HID/4;
    const int N3 = N2 + NLAYERS*MLPD*HID/4;
    const int N4 = N3 + NLAYERS*HID*MLPD/4;
    const int N5 = N4 + NLAYERS*S2*HID;
    const int N6 = N5 + NLAYERS*HID*S2;

    int i = blockIdx.x * blockDim.x + threadIdx.x;
    if (i < N4) {
        const float* src; __half* dst; int j;
        if (i < N0)      { src = x;    dst = g_xr;   j = i; }
        else if (i < N1) { src = embW; dst = g_wE;   j = i - N0; }
        else if (i < N2) { src = outW; dst = g_wOut; j = i - N1; }
        else if (i < N3) { src = Wh;   dst = g_wH;   j = i - N2; }
        else             { src = Wo;   dst = g_wO;   j = i - N3; }
        float4 v = ((const float4*)src)[j];
        ((__half2*)dst)[j*2]   = __floats2half2_rn(v.x, v.y);
        ((__half2*)dst)[j*2+1] = __floats2half2_rn(v.z, v.w);
    } else if (i < N5) {
        int j  = i - N4;
        int k  = j & (HID-1);
        int rr = (j >> 8) & (S2-1);
        int l  = j >> 17;
        int s  = rr >> 1;
        float ga = expf(gl[l*STATEN + s]);
        float v = (rr & 1) ? Bim[((size_t)l*STATEN + s)*HID + k]
                           : Bre[((size_t)l*STATEN + s)*HID + k];
        g_wB[j] = __float2half_rn(v * ga);
    } else if (i < N6) {
        int j  = i - N5;
        int kk = j & (S2-1);
        int hh = (j >> 9) & (HID-1);
        int l  = j >> 17;
        int s  = kk >> 1;
        float v = (kk & 1) ? -Cim[((size_t)l*HID + hh)*STATEN + s]
                           :  Cre[((size_t)l*HID + hh)*STATEN + s];
        g_wC[j] = __float2half_rn(v);
    }
}
#define PREP_TOTAL (M_TOT*INDIM/4 + HID*INDIM/4 + OUTD*HID/4 + NLAYERS*MLPD*HID/4 \
                    + NLAYERS*HID*MLPD/4 + NLAYERS*S2*HID + NLAYERS*HID*S2)

// ==================== fused LRU scan ========================================
__device__ __forceinline__ void lam_of(const float* nu_log, const float* th_log,
                                       int layer, int s, float& lre, float& lim)
{
    float nu = nu_log[layer*STATEN + s];
    float th = th_log[layer*STATEN + s];
    float mag = expf(-expf(nu));
    float ang = expf(th);
    float sv, cv;
    sincosf(ang, &sv, &cv);
    lre = mag * cv;
    lim = mag * sv;
}

// grid: (STATEN/SGRP, BATCHN) = (32,16), block: 512 = 64 chunks x 8 states
// bu chunk cached in registers: phase 3 re-uses phase 1's loaded values
// (bit-identical to re-reading; g_bu unmodified between phases).
__global__ __launch_bounds__(512)
void scan_fused(const float* __restrict__ nu_log, const float* __restrict__ th_log,
                int layer)
{
    __shared__ float se_r[NCH][SGRP], se_i[NCH][SGRP];
    __shared__ float ca_r[NCH][SGRP], ca_i[NCH][SGRP];

    int tid = threadIdx.x;
    int c   = tid >> 3;            // chunk 0..63
    int sl  = tid & (SGRP-1);      // state lane 0..7
    int s   = blockIdx.x * SGRP + sl;
    int b   = blockIdx.y;

    float lre, lim;
    lam_of(nu_log, th_log, layer, s, lre, lim);

    size_t base2 = ((size_t)b * SEQL + (size_t)c * CH) * STATEN + s;
    const __half2* bu2 = (const __half2*)g_bu;
    __half2*       st2 = (__half2*)g_st;

    __half2 buf[CH];   // statically indexed under full unroll -> registers

    // phase 1: load chunk into regs + local scan, keep chunk-end state
    {
        float sr = 0.f, si = 0.f;
        #pragma unroll
        for (int t = 0; t < CH; t++) {
            buf[t] = bu2[base2 + (size_t)t * STATEN];
            float2 u = __half22float2(buf[t]);
            float nr = fmaf(lre, sr, fmaf(-lim, si, u.x));
            float ni = fmaf(lre, si, fmaf( lim, sr, u.y));
            sr = nr; si = ni;
        }
        se_r[c][sl] = sr; se_i[c][sl] = si;
    }
    __syncthreads();

    // phase 2: serial carry combine (first SGRP threads; for them sl == tid)
    if (tid < SGRP) {
        float ar = lre, ai = lim;     // lam^CH via LOG2CH squarings
        #pragma unroll
        for (int q = 0; q < LOG2CH; q++) {
            float nr = ar*ar - ai*ai;
            ai = 2.f * ar * ai;
            ar = nr;
        }
        float cr = 0.f, ci = 0.f;
        #pragma unroll
        for (int c2 = 0; c2 < NCH; c2++) {
            ca_r[c2][sl] = cr; ca_i[c2][sl] = ci;
            float er = se_r[c2][sl], ei = se_i[c2][sl];
            float nr = fmaf(ar, cr, fmaf(-ai, ci, er));
            float ni = fmaf(ar, ci, fmaf( ai, cr, ei));
            cr = nr; ci = ni;
        }
    }
    __syncthreads();

    // phase 3: rescan from registers with carry-in, write fp16 states
    {
        float sr = ca_r[c][sl], si = ca_i[c][sl];
        #pragma unroll
        for (int t = 0; t < CH; t++) {
            float2 u = __half22float2(buf[t]);
            float nr = fmaf(lre, sr, fmaf(-lim, si, u.x));
            float ni = fmaf(lre, si, fmaf( lim, sr, u.y));
            sr = nr; si = ni;
            st2[base2 + (size_t)t * STATEN] = __floats2half2_rn(sr, si);
        }
    }
}

// ==================== driver ================================================
extern "C" void kernel_launch(void* const* d_in, const int* in_sizes, int n_in,
                              void* d_out, int out_size)
{
    (void)in_sizes; (void)n_in; (void)out_size;
    const float* x    = (const float*)d_in[0];
    const float* embW = (const float*)d_in[1];
    const float* embb = (const float*)d_in[2];
    const float* nu   = (const float*)d_in[3];
    const float* th   = (const float*)d_in[4];
    const float* gl   = (const float*)d_in[5];
    const float* Bre  = (const float*)d_in[6];
    const float* Bim  = (const float*)d_in[7];
    const float* Cre  = (const float*)d_in[8];
    const float* Cim  = (const float*)d_in[9];
    const float* Dv   = (const float*)d_in[10];
    const float* Wh   = (const float*)d_in[11];
    const float* bh   = (const float*)d_in[12];
    const float* Wo   = (const float*)d_in[13];
    const float* bo   = (const float*)d_in[14];
    const float* outW = (const float*)d_in[15];
    const float* outb = (const float*)d_in[16];
    float* out = (float*)d_out;

    __half *h, *y, *z, *xr, *wE, *wB, *wC, *wH, *wO, *wOut, *stp, *bup;
    cudaGetSymbolAddress((void**)&h,    g_h);
    cudaGetSymbolAddress((void**)&y,    g_y);
    cudaGetSymbolAddress((void**)&z,    g_z);
    cudaGetSymbolAddress((void**)&xr,   g_xr);
    cudaGetSymbolAddress((void**)&wE,   g_wE);
    cudaGetSymbolAddress((void**)&wB,   g_wB);
    cudaGetSymbolAddress((void**)&wC,   g_wC);
    cudaGetSymbolAddress((void**)&wH,   g_wH);
    cudaGetSymbolAddress((void**)&wO,   g_wO);
    cudaGetSymbolAddress((void**)&wOut, g_wOut);
    cudaGetSymbolAddress((void**)&stp,  g_st);
    cudaGetSymbolAddress((void**)&bup,  g_bu);

    const int SM128 = NSTG*(BM+128)*HSTR*2;   // 81920
    cudaFuncSetAttribute((const void*)gemm_h<128,__half>, cudaFuncAttributeMaxDynamicSharedMemorySize, SM128);
    cudaFuncSetAttribute((const void*)gemm_h<128,float>,  cudaFuncAttributeMaxDynamicSharedMemorySize, SM128);

    dim3 tb(256);
    const int MB = M_TOT / BM;   // 256

    // ---- prep: ONE kernel for all conversions/concats (gamma folded) ----
    prep_all<<<(PREP_TOTAL + 255)/256, tb>>>(x, embW, outW, Wh, Wo, Bre, Bim, Cre, Cim, gl);

    // embedding: h = half(x @ embW^T + embb)
    gemm_h<128,__half><<<dim3(HID/128, MB), tb, SM128>>>(M_TOT, HID, INDIM, xr, wE, embb, (const __half*)nullptr, h, 1);

    for (int l = 0; l < NLAYERS; l++) {
        // bu = h @ Bcat^T   [M, 512] fp16 (gamma pre-applied)
        gemm_h<128,__half><<<dim3(S2/128, MB), tb, SM128>>>(M_TOT, S2, HID, h, wB + (size_t)l*S2*HID,
                                                            (const float*)nullptr, (const __half*)nullptr, bup, 0);
        // fused chunked complex scan (register-cached bu)
        scan_fused<<<dim3(STATEN/SGRP, BATCHN), 512>>>(nu, th, l);

        // y = half([st interleaved] @ wC^T + D*h)
        gemm_h<128,__half><<<dim3(HID/128, MB), tb, SM128>>>(M_TOT, HID, S2, stp, wC + (size_t)l*HID*S2,
                                                             Dv + (size_t)l*HID, h, y, 7);
        // MLP
        gemm_h<128,__half><<<dim3(MLPD/128, MB), tb, SM128>>>(M_TOT, MLPD, HID, y, wH + (size_t)l*MLPD*HID,
                                                              bh + (size_t)l*MLPD, (const __half*)nullptr, z, 2);
        gemm_h<128,__half><<<dim3(HID/128, MB), tb, SM128>>>(M_TOT, HID, MLPD, z, wO + (size_t)l*HID*MLPD,
                                                             bo + (size_t)l*HID, y, h, 3);
    }

    // out = h @ outW^T + outb   (fp32 store)
    gemm_h<128,float><<<dim3(OUTD/128, MB), tb, SM128>>>(M_TOT, OUTD, HID, h, wOut, outb, (const float*)nullptr, out, 1);
}

// round 16
// speedup vs baseline: 1.1008x; 1.0204x over previous
#include <cuda_runtime.h>
#include <cuda_fp16.h>
#include <math.h>
#include <stdint.h>

#define BATCHN  16
#define SEQL    2048
#define INDIM   64
#define HID     256
#define STATEN  256
#define MLPD    1024
#define OUTD    128
#define NLAYERS 4
#define M_TOT   (BATCHN*SEQL)   /* 32768 */
#define CH      32
#define NCH     (SEQL/CH)       /* 64 */
#define LOG2CH  5
#define S2      (2*STATEN)      /* 512 */

// ---------------- scratch (static device globals) ---------------------------
__device__ __half g_h [M_TOT*HID];
__device__ __half g_y [M_TOT*HID];
__device__ __half g_bu[M_TOT*S2];        // interleaved: col 2s = re_s, 2s+1 = im_s (fp16)
__device__ __half g_st[M_TOT*S2];        // interleaved likewise
__device__ __half g_z [M_TOT*MLPD];
__device__ __half g_xr  [M_TOT*INDIM];
__device__ __half g_wE  [HID*INDIM];
__device__ __half g_wB  [NLAYERS*S2*HID];   // row 2s=Bre[s]*ga, 2s+1=Bim[s]*ga
__device__ __half g_wC  [NLAYERS*HID*S2];   // col 2s=Cre[.][s], 2s+1=-Cim[.][s]
__device__ __half g_wH  [NLAYERS*MLPD*HID];
__device__ __half g_wO  [NLAYERS*HID*MLPD];
__device__ __half g_wOut[OUTD*HID];

// ==================== FP16 tensor-core GEMM (R13-proven) ====================
// C[M,N] = epi(A[M,K] @ W[N,K]^T); A,W fp16; accumulate fp32.
// epi: 0 raw | 1 +bias | 2 gelu(+bias) | 3 +bias+resid | 7 + bias[c]*resid
#define BM   128
#define BK   32            /* k elements per stage */
#define HSTR 40            /* padded row stride in halves (80B) — ldmatrix conflict-free */
#define NSTG 4

__device__ __forceinline__ void cp16(uint32_t dst, const void* src){
    asm volatile("cp.async.ca.shared.global [%0], [%1], 16;\n" :: "r"(dst), "l"(src));
}
__device__ __forceinline__ void mma_f16(float* c, const uint32_t* a, const uint32_t* b){
    asm volatile("mma.sync.aligned.m16n8k16.row.col.f32.f16.f16.f32 "
        "{%0,%1,%2,%3}, {%4,%5,%6,%7}, {%8,%9}, {%0,%1,%2,%3};"
        : "+f"(c[0]), "+f"(c[1]), "+f"(c[2]), "+f"(c[3])
        : "r"(a[0]), "r"(a[1]), "r"(a[2]), "r"(a[3]), "r"(b[0]), "r"(b[1]));
}
__device__ __forceinline__ void ldm4(uint32_t& r0, uint32_t& r1, uint32_t& r2, uint32_t& r3,
                                     uint32_t addr){
    asm volatile("ldmatrix.sync.aligned.m8n8.x4.shared.b16 {%0,%1,%2,%3}, [%4];"
        : "=r"(r0), "=r"(r1), "=r"(r2), "=r"(r3) : "r"(addr));
}

template<typename CT>
__device__ __forceinline__ void store2(CT* C, size_t off, float v0, float v1);
template<> __device__ __forceinline__ void store2<__half>(__half* C, size_t off, float v0, float v1){
    *(__half2*)(C + off) = __floats2half2_rn(v0, v1);
}
template<> __device__ __forceinline__ void store2<float>(float* C, size_t off, float v0, float v1){
    C[off] = v0; C[off+1] = v1;
}
template<typename CT>
__device__ __forceinline__ float rd(const CT* p, size_t off);
template<> __device__ __forceinline__ float rd<__half>(const __half* p, size_t off){ return __half2float(p[off]); }
template<> __device__ __forceinline__ float rd<float>(const float* p, size_t off){ return p[off]; }

template<int BN, typename CT>
__global__ __launch_bounds__(256, 2)
void gemm_h(int M, int N, int K,
            const __half* __restrict__ A, const __half* __restrict__ W,
            const float* __restrict__ bias, const CT* __restrict__ resid,
            CT* __restrict__ C, int epi)
{
    constexpr int NT    = BN/32;                 // n fragments per warp (4)
    constexpr int NP    = NT/2;
    constexpr int NLB   = BN/64;
    constexpr int SLOTA = BM*HSTR;               // halves
    constexpr int SLOTB = BN*HSTR;

    extern __shared__ __align__(16) __half smem[];
    __half* As = smem;
    __half* Bs = smem + NSTG*SLOTA;

    int tid  = threadIdx.x;
    int lane = tid & 31;
    int wid  = tid >> 5;
    int gr   = lane >> 2;
    int ct   = lane & 3;
    int wm   = (wid >> 2) * 64;
    int wn   = (wid & 3) * (BN/4);
    int row0 = blockIdx.y * BM;
    int col0 = blockIdx.x * BN;

    uint32_t sAb = (uint32_t)__cvta_generic_to_shared(As);
    uint32_t sBb = (uint32_t)__cvta_generic_to_shared(Bs);

    // ldmatrix per-lane base addresses (within stage 0)
    uint32_t aBase = sAb + (uint32_t)((wm + ((lane>>3)&1)*8 + (lane&7))*HSTR)*2
                   + (uint32_t)(lane>>4)*16;
    uint32_t bBase = sBb + (uint32_t)((wn + (lane>>4)*8 + (lane&7))*HSTR)*2
                   + (uint32_t)((lane>>3)&1)*16;

    float acc[4][NT][4];
    #pragma unroll
    for (int i=0;i<4;i++)
        #pragma unroll
        for (int j=0;j<NT;j++)
            #pragma unroll
            for (int q=0;q<4;q++) acc[i][j][q] = 0.f;

    int nk = K / BK;

    // guarded stage load: only touches memory when kt < nk; ALWAYS commits a
    // group so wait_group accounting stays consistent.
    auto load_stage = [&](int kt){
        if (kt < nk) {
            int slot = kt % NSTG;
            int k0 = kt * BK;
            #pragma unroll
            for (int j = 0; j < 2; j++) {
                int id = tid + j*256;
                int r = id >> 2, kb = id & 3;
                cp16(sAb + (slot*SLOTA + r*HSTR)*2 + kb*16,
                     A + (size_t)(row0 + r)*K + k0 + kb*8);
            }
            #pragma unroll
            for (int j = 0; j < NLB; j++) {
                int id = tid + j*256;
                int r = id >> 2, kb = id & 3;
                cp16(sBb + (slot*SLOTB + r*HSTR)*2 + kb*16,
                     W + (size_t)(col0 + r)*K + k0 + kb*8);
            }
        }
        asm volatile("cp.async.commit_group;\n");
    };

    load_stage(0);
    load_stage(1);
    load_stage(2);

    for (int kt = 0; kt < nk; kt++) {
        asm volatile("cp.async.wait_group 2;\n");
        __syncthreads();
        load_stage(kt + 3);

        int slot = kt % NSTG;
        uint32_t aSlot = aBase + slot*SLOTA*2;
        uint32_t bSlot = bBase + slot*SLOTB*2;
        #pragma unroll
        for (int ks = 0; ks < 2; ks++) {     // two k16 steps per stage
            uint32_t ua[4][4], ub[NT][2];
            #pragma unroll
            for (int mt = 0; mt < 4; mt++)
                ldm4(ua[mt][0], ua[mt][1], ua[mt][2], ua[mt][3],
                     aSlot + mt*16*HSTR*2 + ks*32);
            #pragma unroll
            for (int p = 0; p < NP; p++)
                ldm4(ub[2*p][0], ub[2*p][1], ub[2*p+1][0], ub[2*p+1][1],
                     bSlot + p*16*HSTR*2 + ks*32);
            #pragma unroll
            for (int mt = 0; mt < 4; mt++)
                #pragma unroll
                for (int nt = 0; nt < NT; nt++)
                    mma_f16(acc[mt][nt], ua[mt], ub[nt]);
        }
    }

    #pragma unroll
    for (int mt = 0; mt < 4; mt++) {
        #pragma unroll
        for (int half = 0; half < 2; half++) {
            int r = row0 + wm + mt*16 + gr + half*8;
            size_t ro = (size_t)r * N;
            #pragma unroll
            for (int nt = 0; nt < NT; nt++) {
                int cc = col0 + wn + nt*8 + ct*2;
                float v0 = acc[mt][nt][half*2 + 0];
                float v1 = acc[mt][nt][half*2 + 1];
                if (epi == 1) {
                    v0 += bias[cc]; v1 += bias[cc+1];
                } else if (epi == 2) {
                    float t0 = v0 + bias[cc], t1 = v1 + bias[cc+1];
                    v0 = 0.5f * t0 * (1.0f + erff(t0 * 0.70710678118654752f));
                    v1 = 0.5f * t1 * (1.0f + erff(t1 * 0.70710678118654752f));
                } else if (epi == 3) {
                    v0 += bias[cc]   + rd<CT>(resid, ro+cc);
                    v1 += bias[cc+1] + rd<CT>(resid, ro+cc+1);
                } else if (epi == 7) {
                    v0 += bias[cc]   * rd<CT>(resid, ro+cc);
                    v1 += bias[cc+1] * rd<CT>(resid, ro+cc+1);
                }
                store2<CT>(C, ro + cc, v0, v1);
            }
        }
    }
}

// ==================== unified prep kernel ===================================
__global__ void prep_all(const float* __restrict__ x,    const float* __restrict__ embW,
                         const float* __restrict__ outW, const float* __restrict__ Wh,
                         const float* __restrict__ Wo,   const float* __restrict__ Bre,
                         const float* __restrict__ Bim,  const float* __restrict__ Cre,
                         const float* __restrict__ Cim,  const float* __restrict__ gl)
{
    const int N0 = M_TOT*INDIM/4;
    const int N1 = N0 + HID*INDIM/4;
    const int N2 = N1 + OUTD*HID/4;
    const int N3 = N2 + NLAYERS*MLPD*HID/4;
    const int N4 = N3 + NLAYERS*HID*MLPD/4;
    const int N5 = N4 + NLAYERS*S2*HID;
    const int N6 = N5 + NLAYERS*HID*S2;

    int i = blockIdx.x * blockDim.x + threadIdx.x;
    if (i < N4) {
        const float* src; __half* dst; int j;
        if (i < N0)      { src = x;    dst = g_xr;   j = i; }
        else if (i < N1) { src = embW; dst = g_wE;   j = i - N0; }
        else if (i < N2) { src = outW; dst = g_wOut; j = i - N1; }
        else if (i < N3) { src = Wh;   dst = g_wH;   j = i - N2; }
        else             { src = Wo;   dst = g_wO;   j = i - N3; }
        float4 v = ((const float4*)src)[j];
        ((__half2*)dst)[j*2]   = __floats2half2_rn(v.x, v.y);
        ((__half2*)dst)[j*2+1] = __floats2half2_rn(v.z, v.w);
    } else if (i < N5) {
        int j  = i - N4;
        int k  = j & (HID-1);
        int rr = (j >> 8) & (S2-1);
        int l  = j >> 17;
        int s  = rr >> 1;
        float ga = expf(gl[l*STATEN + s]);
        float v = (rr & 1) ? Bim[((size_t)l*STATEN + s)*HID + k]
                           : Bre[((size_t)l*STATEN + s)*HID + k];
        g_wB[j] = __float2half_rn(v * ga);
    } else if (i < N6) {
        int j  = i - N5;
        int kk = j & (S2-1);
        int hh = (j >> 9) & (HID-1);
        int l  = j >> 17;
        int s  = kk >> 1;
        float v = (kk & 1) ? -Cim[((size_t)l*HID + hh)*STATEN + s]
                           :  Cre[((size_t)l*HID + hh)*STATEN + s];
        g_wC[j] = __float2half_rn(v);
    }
}
#define PREP_TOTAL (M_TOT*INDIM/4 + HID*INDIM/4 + OUTD*HID/4 + NLAYERS*MLPD*HID/4 \
                    + NLAYERS*HID*MLPD/4 + NLAYERS*S2*HID + NLAYERS*HID*S2)

// ==================== fused LRU scan ========================================
__device__ __forceinline__ void lam_of(const float* nu_log, const float* th_log,
                                       int layer, int s, float& lre, float& lim)
{
    float nu = nu_log[layer*STATEN + s];
    float th = th_log[layer*STATEN + s];
    float mag = expf(-expf(nu));
    float ang = expf(th);
    float sv, cv;
    sincosf(ang, &sv, &cv);
    lre = mag * cv;
    lim = mag * sv;
}

// grid: (STATEN/16, BATCHN) = (16,16), block: 512 = 64 chunks x 8 thread-pairs.
// Each thread processes TWO adjacent states (independent chains -> 2x ILP,
// 8-byte vectorized loads/stores). Per-state arithmetic identical to R13.
__global__ __launch_bounds__(512)
void scan_fused(const float* __restrict__ nu_log, const float* __restrict__ th_log,
                int layer)
{
    __shared__ float se_r[NCH][16], se_i[NCH][16];
    __shared__ float ca_r[NCH][16], ca_i[NCH][16];

    int tid = threadIdx.x;
    int c   = tid >> 3;            // chunk 0..63
    int sp  = tid & 7;             // state-pair lane 0..7
    int s0  = blockIdx.x * 16 + sp*2;
    int b   = blockIdx.y;

    float lre0, lim0, lre1, lim1;
    lam_of(nu_log, th_log, layer, s0,     lre0, lim0);
    lam_of(nu_log, th_log, layer, s0 + 1, lre1, lim1);

    // index in half2 units; s0 even -> byte offset 8-aligned for uint2
    size_t base2 = ((size_t)b * SEQL + (size_t)c * CH) * STATEN + s0;
    const __half2* bu2 = (const __half2*)g_bu;
    __half2*       st2 = (__half2*)g_st;

    // phase 1: local scans (two independent chains), keep chunk-end states
    {
        float sr0 = 0.f, si0 = 0.f, sr1 = 0.f, si1 = 0.f;
        #pragma unroll 4
        for (int t = 0; t < CH; t++) {
            uint2 v = *(const uint2*)(bu2 + base2 + (size_t)t * STATEN);
            float2 u0 = __half22float2(*(const __half2*)&v.x);
            float2 u1 = __half22float2(*(const __half2*)&v.y);
            float nr0 = fmaf(lre0, sr0, fmaf(-lim0, si0, u0.x));
            float ni0 = fmaf(lre0, si0, fmaf( lim0, sr0, u0.y));
            float nr1 = fmaf(lre1, sr1, fmaf(-lim1, si1, u1.x));
            float ni1 = fmaf(lre1, si1, fmaf( lim1, sr1, u1.y));
            sr0 = nr0; si0 = ni0; sr1 = nr1; si1 = ni1;
        }
        se_r[c][sp*2]   = sr0; se_i[c][sp*2]   = si0;
        se_r[c][sp*2+1] = sr1; se_i[c][sp*2+1] = si1;
    }
    __syncthreads();

    // phase 2: serial carry combine (threads 0..7; for them c==0 and sp==tid,
    // so lam registers match their states)
    if (tid < 8) {
        float ar0 = lre0, ai0 = lim0, ar1 = lre1, ai1 = lim1;  // lam^CH
        #pragma unroll
        for (int q = 0; q < LOG2CH; q++) {
            float nr0 = ar0*ar0 - ai0*ai0; ai0 = 2.f*ar0*ai0; ar0 = nr0;
            float nr1 = ar1*ar1 - ai1*ai1; ai1 = 2.f*ar1*ai1; ar1 = nr1;
        }
        float cr0 = 0.f, ci0 = 0.f, cr1 = 0.f, ci1 = 0.f;
        #pragma unroll
        for (int c2 = 0; c2 < NCH; c2++) {
            ca_r[c2][sp*2]   = cr0; ca_i[c2][sp*2]   = ci0;
            ca_r[c2][sp*2+1] = cr1; ca_i[c2][sp*2+1] = ci1;
            float er0 = se_r[c2][sp*2],   ei0 = se_i[c2][sp*2];
            float er1 = se_r[c2][sp*2+1], ei1 = se_i[c2][sp*2+1];
            float nr0 = fmaf(ar0, cr0, fmaf(-ai0, ci0, er0));
            float ni0 = fmaf(ar0, ci0, fmaf( ai0, cr0, ei0));
            float nr1 = fmaf(ar1, cr1, fmaf(-ai1, ci1, er1));
            float ni1 = fmaf(ar1, ci1, fmaf( ai1, cr1, ei1));
            cr0 = nr0; ci0 = ni0; cr1 = nr1; ci1 = ni1;
        }
    }
    __syncthreads();

    // phase 3: rescan with carry-in, write fp16 states (vectorized)
    {
        float sr0 = ca_r[c][sp*2],   si0 = ca_i[c][sp*2];
        float sr1 = ca_r[c][sp*2+1], si1 = ca_i[c][sp*2+1];
        #pragma unroll 4
        for (int t = 0; t < CH; t++) {
            uint2 v = *(const uint2*)(bu2 + base2 + (size_t)t * STATEN);
            float2 u0 = __half22float2(*(const __half2*)&v.x);
            float2 u1 = __half22float2(*(const __half2*)&v.y);
            float nr0 = fmaf(lre0, sr0, fmaf(-lim0, si0, u0.x));
            float ni0 = fmaf(lre0, si0, fmaf( lim0, sr0, u0.y));
            float nr1 = fmaf(lre1, sr1, fmaf(-lim1, si1, u1.x));
            float ni1 = fmaf(lre1, si1, fmaf( lim1, sr1, u1.y));
            sr0 = nr0; si0 = ni0; sr1 = nr1; si1 = ni1;
            uint2 o;
            *(__half2*)&o.x = __floats2half2_rn(sr0, si0);
            *(__half2*)&o.y = __floats2half2_rn(sr1, si1);
            *(uint2*)(st2 + base2 + (size_t)t * STATEN) = o;
        }
    }
}

// ==================== driver ================================================
extern "C" void kernel_launch(void* const* d_in, const int* in_sizes, int n_in,
                              void* d_out, int out_size)
{
    (void)in_sizes; (void)n_in; (void)out_size;
    const float* x    = (const float*)d_in[0];
    const float* embW = (const float*)d_in[1];
    const float* embb = (const float*)d_in[2];
    const float* nu   = (const float*)d_in[3];
    const float* th   = (const float*)d_in[4];
    const float* gl   = (const float*)d_in[5];
    const float* Bre  = (const float*)d_in[6];
    const float* Bim  = (const float*)d_in[7];
    const float* Cre  = (const float*)d_in[8];
    const float* Cim  = (const float*)d_in[9];
    const float* Dv   = (const float*)d_in[10];
    const float* Wh   = (const float*)d_in[11];
    const float* bh   = (const float*)d_in[12];
    const float* Wo   = (const float*)d_in[13];
    const float* bo   = (const float*)d_in[14];
    const float* outW = (const float*)d_in[15];
    const float* outb = (const float*)d_in[16];
    float* out = (float*)d_out;

    __half *h, *y, *z, *xr, *wE, *wB, *wC, *wH, *wO, *wOut, *stp, *bup;
    cudaGetSymbolAddress((void**)&h,    g_h);
    cudaGetSymbolAddress((void**)&y,    g_y);
    cudaGetSymbolAddress((void**)&z,    g_z);
    cudaGetSymbolAddress((void**)&xr,   g_xr);
    cudaGetSymbolAddress((void**)&wE,   g_wE);
    cudaGetSymbolAddress((void**)&wB,   g_wB);
    cudaGetSymbolAddress((void**)&wC,   g_wC);
    cudaGetSymbolAddress((void**)&wH,   g_wH);
    cudaGetSymbolAddress((void**)&wO,   g_wO);
    cudaGetSymbolAddress((void**)&wOut, g_wOut);
    cudaGetSymbolAddress((void**)&stp,  g_st);
    cudaGetSymbolAddress((void**)&bup,  g_bu);

    const int SM128 = NSTG*(BM+128)*HSTR*2;   // 81920
    cudaFuncSetAttribute((const void*)gemm_h<128,__half>, cudaFuncAttributeMaxDynamicSharedMemorySize, SM128);
    cudaFuncSetAttribute((const void*)gemm_h<128,float>,  cudaFuncAttributeMaxDynamicSharedMemorySize, SM128);

    dim3 tb(256);
    const int MB = M_TOT / BM;   // 256

    // ---- prep: ONE kernel for all conversions/concats (gamma folded) ----
    prep_all<<<(PREP_TOTAL + 255)/256, tb>>>(x, embW, outW, Wh, Wo, Bre, Bim, Cre, Cim, gl);

    // embedding: h = half(x @ embW^T + embb)
    gemm_h<128,__half><<<dim3(HID/128, MB), tb, SM128>>>(M_TOT, HID, INDIM, xr, wE, embb, (const __half*)nullptr, h, 1);

    for (int l = 0; l < NLAYERS; l++) {
        // bu = h @ Bcat^T   [M, 512] fp16 (gamma pre-applied)
        gemm_h<128,__half><<<dim3(S2/128, MB), tb, SM128>>>(M_TOT, S2, HID, h, wB + (size_t)l*S2*HID,
                                                            (const float*)nullptr, (const __half*)nullptr, bup, 0);
        // fused chunked complex scan (2 states/thread)
        scan_fused<<<dim3(STATEN/16, BATCHN), 512>>>(nu, th, l);

        // y = half([st interleaved] @ wC^T + D*h)
        gemm_h<128,__half><<<dim3(HID/128, MB), tb, SM128>>>(M_TOT, HID, S2, stp, wC + (size_t)l*HID*S2,
                                                             Dv + (size_t)l*HID, h, y, 7);
        // MLP
        gemm_h<128,__half><<<dim3(MLPD/128, MB), tb, SM128>>>(M_TOT, MLPD, HID, y, wH + (size_t)l*MLPD*HID,
                                                              bh + (size_t)l*MLPD, (const __half*)nullptr, z, 2);
        gemm_h<128,__half><<<dim3(HID/128, MB), tb, SM128>>>(M_TOT, HID, MLPD, z, wO + (size_t)l*HID*MLPD,
                                                             bo + (size_t)l*HID, y, h, 3);
    }

    // out = h @ outW^T + outb   (fp32 store)
    gemm_h<128,float><<<dim3(OUTD/128, MB), tb, SM128>>>(M_TOT, OUTD, HID, h, wOut, outb, (const float*)nullptr, out, 1);
}

// round 17
// speedup vs baseline: 1.1524x; 1.0469x over previous
#include <cuda_runtime.h>
#include <cuda_fp16.h>
#include <math.h>
#include <stdint.h>

#define BATCHN  16
#define SEQL    2048
#define INDIM   64
#define HID     256
#define STATEN  256
#define MLPD    1024
#define OUTD    128
#define NLAYERS 4
#define M_TOT   (BATCHN*SEQL)   /* 32768 */
#define CH      32
#define NCH     (SEQL/CH)       /* 64 */
#define LOG2CH  5
#define SGRP    8               /* states per scan block */
#define S2      (2*STATEN)      /* 512 */

// ---------------- scratch (static device globals) ---------------------------
__device__ __half g_h [M_TOT*HID];
__device__ __half g_y [M_TOT*HID];
__device__ __half g_bu[M_TOT*S2];        // interleaved: col 2s = re_s, 2s+1 = im_s (fp16)
__device__ __half g_st[M_TOT*S2];        // interleaved likewise
__device__ __half g_z [M_TOT*MLPD];
__device__ __half g_xr  [M_TOT*INDIM];
__device__ __half g_wE  [HID*INDIM];
__device__ __half g_wB  [NLAYERS*S2*HID];   // row 2s=Bre[s]*ga, 2s+1=Bim[s]*ga
__device__ __half g_wC  [NLAYERS*HID*S2];   // col 2s=Cre[.][s], 2s+1=-Cim[.][s]
__device__ __half g_wH  [NLAYERS*MLPD*HID];
__device__ __half g_wO  [NLAYERS*HID*MLPD];
__device__ __half g_wOut[OUTD*HID];

// ==================== FP16 tensor-core GEMM =================================
// C[M,N] = EPI(A[M,K] @ W[N,K]^T); A,W fp16; accumulate fp32.
// EPI: 0 raw | 1 +bias | 2 gelu(+bias) | 3 +bias+resid | 7 + bias[c]*resid
#define BM   128
#define BK   32            /* k elements per stage */
#define HSTR 40            /* padded row stride in halves (80B) — ldmatrix conflict-free */
#define NSTG 4

__device__ __forceinline__ void cp16(uint32_t dst, const void* src){
    asm volatile("cp.async.cg.shared.global [%0], [%1], 16;\n" :: "r"(dst), "l"(src));
}
__device__ __forceinline__ void mma_f16(float* c, const uint32_t* a, const uint32_t* b){
    asm volatile("mma.sync.aligned.m16n8k16.row.col.f32.f16.f16.f32 "
        "{%0,%1,%2,%3}, {%4,%5,%6,%7}, {%8,%9}, {%0,%1,%2,%3};"
        : "+f"(c[0]), "+f"(c[1]), "+f"(c[2]), "+f"(c[3])
        : "r"(a[0]), "r"(a[1]), "r"(a[2]), "r"(a[3]), "r"(b[0]), "r"(b[1]));
}
__device__ __forceinline__ void ldm4(uint32_t& r0, uint32_t& r1, uint32_t& r2, uint32_t& r3,
                                     uint32_t addr){
    asm volatile("ldmatrix.sync.aligned.m8n8.x4.shared.b16 {%0,%1,%2,%3}, [%4];"
        : "=r"(r0), "=r"(r1), "=r"(r2), "=r"(r3) : "r"(addr));
}

template<typename CT>
__device__ __forceinline__ void store2(CT* C, size_t off, float v0, float v1);
template<> __device__ __forceinline__ void store2<__half>(__half* C, size_t off, float v0, float v1){
    *(__half2*)(C + off) = __floats2half2_rn(v0, v1);
}
template<> __device__ __forceinline__ void store2<float>(float* C, size_t off, float v0, float v1){
    C[off] = v0; C[off+1] = v1;
}
template<typename CT>
__device__ __forceinline__ float rd(const CT* p, size_t off);
template<> __device__ __forceinline__ float rd<__half>(const __half* p, size_t off){ return __half2float(p[off]); }
template<> __device__ __forceinline__ float rd<float>(const float* p, size_t off){ return p[off]; }

template<int BN, typename CT, int EPI>
__global__ __launch_bounds__(256, 2)
void gemm_h(int M, int N, int K,
            const __half* __restrict__ A, const __half* __restrict__ W,
            const float* __restrict__ bias, const CT* __restrict__ resid,
            CT* __restrict__ C)
{
    constexpr int NT    = BN/32;                 // n fragments per warp (4)
    constexpr int NP    = NT/2;
    constexpr int NLB   = BN/64;
    constexpr int SLOTA = BM*HSTR;               // halves
    constexpr int SLOTB = BN*HSTR;

    extern __shared__ __align__(16) __half smem[];
    __half* As = smem;
    __half* Bs = smem + NSTG*SLOTA;

    int tid  = threadIdx.x;
    int lane = tid & 31;
    int wid  = tid >> 5;
    int gr   = lane >> 2;
    int ct   = lane & 3;
    int wm   = (wid >> 2) * 64;
    int wn   = (wid & 3) * (BN/4);
    int row0 = blockIdx.y * BM;
    int col0 = blockIdx.x * BN;

    uint32_t sAb = (uint32_t)__cvta_generic_to_shared(As);
    uint32_t sBb = (uint32_t)__cvta_generic_to_shared(Bs);

    // ldmatrix per-lane base addresses (within stage 0)
    uint32_t aBase = sAb + (uint32_t)((wm + ((lane>>3)&1)*8 + (lane&7))*HSTR)*2
                   + (uint32_t)(lane>>4)*16;
    uint32_t bBase = sBb + (uint32_t)((wn + (lane>>4)*8 + (lane&7))*HSTR)*2
                   + (uint32_t)((lane>>3)&1)*16;

    float acc[4][NT][4];
    #pragma unroll
    for (int i=0;i<4;i++)
        #pragma unroll
        for (int j=0;j<NT;j++)
            #pragma unroll
            for (int q=0;q<4;q++) acc[i][j][q] = 0.f;

    int nk = K / BK;

    // guarded stage load: only touches memory when kt < nk; ALWAYS commits a
    // group so wait_group accounting stays consistent.
    auto load_stage = [&](int kt){
        if (kt < nk) {
            int slot = kt % NSTG;
            int k0 = kt * BK;
            #pragma unroll
            for (int j = 0; j < 2; j++) {
                int id = tid + j*256;
                int r = id >> 2, kb = id & 3;
                cp16(sAb + (slot*SLOTA + r*HSTR)*2 + kb*16,
                     A + (size_t)(row0 + r)*K + k0 + kb*8);
            }
            #pragma unroll
            for (int j = 0; j < NLB; j++) {
                int id = tid + j*256;
                int r = id >> 2, kb = id & 3;
                cp16(sBb + (slot*SLOTB + r*HSTR)*2 + kb*16,
                     W + (size_t)(col0 + r)*K + k0 + kb*8);
            }
        }
        asm volatile("cp.async.commit_group;\n");
    };

    load_stage(0);
    load_stage(1);
    load_stage(2);

    for (int kt = 0; kt < nk; kt++) {
        asm volatile("cp.async.wait_group 2;\n");
        __syncthreads();
        load_stage(kt + 3);

        int slot = kt % NSTG;
        uint32_t aSlot = aBase + slot*SLOTA*2;
        uint32_t bSlot = bBase + slot*SLOTB*2;
        #pragma unroll
        for (int ks = 0; ks < 2; ks++) {     // two k16 steps per stage
            uint32_t ua[4][4], ub[NT][2];
            #pragma unroll
            for (int mt = 0; mt < 4; mt++)
                ldm4(ua[mt][0], ua[mt][1], ua[mt][2], ua[mt][3],
                     aSlot + mt*16*HSTR*2 + ks*32);
            #pragma unroll
            for (int p = 0; p < NP; p++)
                ldm4(ub[2*p][0], ub[2*p][1], ub[2*p+1][0], ub[2*p+1][1],
                     bSlot + p*16*HSTR*2 + ks*32);
            #pragma unroll
            for (int mt = 0; mt < 4; mt++)
                #pragma unroll
                for (int nt = 0; nt < NT; nt++)
                    mma_f16(acc[mt][nt], ua[mt], ub[nt]);
        }
    }

    #pragma unroll
    for (int mt = 0; mt < 4; mt++) {
        #pragma unroll
        for (int half = 0; half < 2; half++) {
            int r = row0 + wm + mt*16 + gr + half*8;
            size_t ro = (size_t)r * N;
            #pragma unroll
            for (int nt = 0; nt < NT; nt++) {
                int cc = col0 + wn + nt*8 + ct*2;
                float v0 = acc[mt][nt][half*2 + 0];
                float v1 = acc[mt][nt][half*2 + 1];
                if (EPI == 1) {
                    v0 += bias[cc]; v1 += bias[cc+1];
                } else if (EPI == 2) {
                    float t0 = v0 + bias[cc], t1 = v1 + bias[cc+1];
                    v0 = 0.5f * t0 * (1.0f + erff(t0 * 0.70710678118654752f));
                    v1 = 0.5f * t1 * (1.0f + erff(t1 * 0.70710678118654752f));
                } else if (EPI == 3) {
                    v0 += bias[cc]   + rd<CT>(resid, ro+cc);
                    v1 += bias[cc+1] + rd<CT>(resid, ro+cc+1);
                } else if (EPI == 7) {
                    v0 += bias[cc]   * rd<CT>(resid, ro+cc);
                    v1 += bias[cc+1] * rd<CT>(resid, ro+cc+1);
                }
                store2<CT>(C, ro + cc, v0, v1);
            }
        }
    }
}

// ==================== unified prep kernel ===================================
__global__ void prep_all(const float* __restrict__ x,    const float* __restrict__ embW,
                         const float* __restrict__ outW, const float* __restrict__ Wh,
                         const float* __restrict__ Wo,   const float* __restrict__ Bre,
                         const float* __restrict__ Bim,  const float* __restrict__ Cre,
                         const float* __restrict__ Cim,  const float* __restrict__ gl)
{
    const int N0 = M_TOT*INDIM/4;
    const int N1 = N0 + HID*INDIM/4;
    const int N2 = N1 + OUTD*HID/4;
    const int N3 = N2 + NLAYERS*MLPD*HID/4;
    const int N4 = N3 + NLAYERS*HID*MLPD/4;
    const int N5 = N4 + NLAYERS*S2*HID;
    const int N6 = N5 + NLAYERS*HID*S2;

    int i = blockIdx.x * blockDim.x + threadIdx.x;
    if (i < N4) {
        const float* src; __half* dst; int j;
        if (i < N0)      { src = x;    dst = g_xr;   j = i; }
        else if (i < N1) { src = embW; dst = g_wE;   j = i - N0; }
        else if (i < N2) { src = outW; dst = g_wOut; j = i - N1; }
        else if (i < N3) { src = Wh;   dst = g_wH;   j = i - N2; }
        else             { src = Wo;   dst = g_wO;   j = i - N3; }
        float4 v = ((const float4*)src)[j];
        ((__half2*)dst)[j*2]   = __floats2half2_rn(v.x, v.y);
        ((__half2*)dst)[j*2+1] = __floats2half2_rn(v.z, v.w);
    } else if (i < N5) {
        int j  = i - N4;
        int k  = j & (HID-1);
        int rr = (j >> 8) & (S2-1);
        int l  = j >> 17;
        int s  = rr >> 1;
        float ga = expf(gl[l*STATEN + s]);
        float v = (rr & 1) ? Bim[((size_t)l*STATEN + s)*HID + k]
                           : Bre[((size_t)l*STATEN + s)*HID + k];
        g_wB[j] = __float2half_rn(v * ga);
    } else if (i < N6) {
        int j  = i - N5;
        int kk = j & (S2-1);
        int hh = (j >> 9) & (HID-1);
        int l  = j >> 17;
        int s  = kk >> 1;
        float v = (kk & 1) ? -Cim[((size_t)l*HID + hh)*STATEN + s]
                           :  Cre[((size_t)l*HID + hh)*STATEN + s];
        g_wC[j] = __float2half_rn(v);
    }
}
#define PREP_TOTAL (M_TOT*INDIM/4 + HID*INDIM/4 + OUTD*HID/4 + NLAYERS*MLPD*HID/4 \
                    + NLAYERS*HID*MLPD/4 + NLAYERS*S2*HID + NLAYERS*HID*S2)

// ==================== fused LRU scan (R13-proven) ===========================
__device__ __forceinline__ void lam_of(const float* nu_log, const float* th_log,
                                       int layer, int s, float& lre, float& lim)
{
    float nu = nu_log[layer*STATEN + s];
    float th = th_log[layer*STATEN + s];
    float mag = expf(-expf(nu));
    float ang = expf(th);
    float sv, cv;
    sincosf(ang, &sv, &cv);
    lre = mag * cv;
    lim = mag * sv;
}

// grid: (STATEN/SGRP, BATCHN) = (32,16), block: 512 = 64 chunks x 8 states
// WAIT — R13 used SGRP=8 with 512 blocks? No: R13 was SGRP=8? R13: SGRP=16,
// block 1024 = 64 chunks x 16 states, grid (16,16). Restored exactly below.
__global__ __launch_bounds__(1024)
void scan_fused(const float* __restrict__ nu_log, const float* __restrict__ th_log,
                int layer)
{
    __shared__ float se_r[NCH][16], se_i[NCH][16];
    __shared__ float ca_r[NCH][16], ca_i[NCH][16];

    int tid = threadIdx.x;
    int c   = tid >> 4;            // chunk 0..63
    int sl  = tid & 15;            // state lane 0..15
    int s   = blockIdx.x * 16 + sl;
    int b   = blockIdx.y;

    float lre, lim;
    lam_of(nu_log, th_log, layer, s, lre, lim);

    size_t base2 = ((size_t)b * SEQL + (size_t)c * CH) * STATEN + s;
    const __half2* bu2 = (const __half2*)g_bu;
    __half2*       st2 = (__half2*)g_st;

    // phase 1: local scan, keep chunk-end state
    {
        float sr = 0.f, si = 0.f;
        #pragma unroll 4
        for (int t = 0; t < CH; t++) {
            float2 u = __half22float2(bu2[base2 + (size_t)t * STATEN]);
            float nr = fmaf(lre, sr, fmaf(-lim, si, u.x));
            float ni = fmaf(lre, si, fmaf( lim, sr, u.y));
            sr = nr; si = ni;
        }
        se_r[c][sl] = sr; se_i[c][sl] = si;
    }
    __syncthreads();

    // phase 2: serial carry combine (first 16 threads; for them sl == tid)
    if (tid < 16) {
        float ar = lre, ai = lim;     // lam^CH via LOG2CH squarings
        #pragma unroll
        for (int q = 0; q < LOG2CH; q++) {
            float nr = ar*ar - ai*ai;
            ai = 2.f * ar * ai;
            ar = nr;
        }
        float cr = 0.f, ci = 0.f;
        #pragma unroll
        for (int c2 = 0; c2 < NCH; c2++) {
            ca_r[c2][sl] = cr; ca_i[c2][sl] = ci;
            float er = se_r[c2][sl], ei = se_i[c2][sl];
            float nr = fmaf(ar, cr, fmaf(-ai, ci, er));
            float ni = fmaf(ar, ci, fmaf( ai, cr, ei));
            cr = nr; ci = ni;
        }
    }
    __syncthreads();

    // phase 3: rescan with carry-in, write fp16 states
    {
        float sr = ca_r[c][sl], si = ca_i[c][sl];
        #pragma unroll 4
        for (int t = 0; t < CH; t++) {
            float2 u = __half22float2(bu2[base2 + (size_t)t * STATEN]);
            float nr = fmaf(lre, sr, fmaf(-lim, si, u.x));
            float ni = fmaf(lre, si, fmaf( lim, sr, u.y));
            sr = nr; si = ni;
            st2[base2 + (size_t)t * STATEN] = __floats2half2_rn(sr, si);
        }
    }
}

// ==================== driver ================================================
extern "C" void kernel_launch(void* const* d_in, const int* in_sizes, int n_in,
                              void* d_out, int out_size)
{
    (void)in_sizes; (void)n_in; (void)out_size;
    const float* x    = (const float*)d_in[0];
    const float* embW = (const float*)d_in[1];
    const float* embb = (const float*)d_in[2];
    const float* nu   = (const float*)d_in[3];
    const float* th   = (const float*)d_in[4];
    const float* gl   = (const float*)d_in[5];
    const float* Bre  = (const float*)d_in[6];
    const float* Bim  = (const float*)d_in[7];
    const float* Cre  = (const float*)d_in[8];
    const float* Cim  = (const float*)d_in[9];
    const float* Dv   = (const float*)d_in[10];
    const float* Wh   = (const float*)d_in[11];
    const float* bh   = (const float*)d_in[12];
    const float* Wo   = (const float*)d_in[13];
    const float* bo   = (const float*)d_in[14];
    const float* outW = (const float*)d_in[15];
    const float* outb = (const float*)d_in[16];
    float* out = (float*)d_out;

    __half *h, *y, *z, *xr, *wE, *wB, *wC, *wH, *wO, *wOut, *stp, *bup;
    cudaGetSymbolAddress((void**)&h,    g_h);
    cudaGetSymbolAddress((void**)&y,    g_y);
    cudaGetSymbolAddress((void**)&z,    g_z);
    cudaGetSymbolAddress((void**)&xr,   g_xr);
    cudaGetSymbolAddress((void**)&wE,   g_wE);
    cudaGetSymbolAddress((void**)&wB,   g_wB);
    cudaGetSymbolAddress((void**)&wC,   g_wC);
    cudaGetSymbolAddress((void**)&wH,   g_wH);
    cudaGetSymbolAddress((void**)&wO,   g_wO);
    cudaGetSymbolAddress((void**)&wOut, g_wOut);
    cudaGetSymbolAddress((void**)&stp,  g_st);
    cudaGetSymbolAddress((void**)&bup,  g_bu);

    const int SM128 = NSTG*(BM+128)*HSTR*2;   // 81920
    cudaFuncSetAttribute((const void*)gemm_h<128,__half,0>, cudaFuncAttributeMaxDynamicSharedMemorySize, SM128);
    cudaFuncSetAttribute((const void*)gemm_h<128,__half,1>, cudaFuncAttributeMaxDynamicSharedMemorySize, SM128);
    cudaFuncSetAttribute((const void*)gemm_h<128,__half,2>, cudaFuncAttributeMaxDynamicSharedMemorySize, SM128);
    cudaFuncSetAttribute((const void*)gemm_h<128,__half,3>, cudaFuncAttributeMaxDynamicSharedMemorySize, SM128);
    cudaFuncSetAttribute((const void*)gemm_h<128,__half,7>, cudaFuncAttributeMaxDynamicSharedMemorySize, SM128);
    cudaFuncSetAttribute((const void*)gemm_h<128,float,1>,  cudaFuncAttributeMaxDynamicSharedMemorySize, SM128);

    dim3 tb(256);
    const int MB = M_TOT / BM;   // 256

    // ---- prep: ONE kernel for all conversions/concats (gamma folded) ----
    prep_all<<<(PREP_TOTAL + 255)/256, tb>>>(x, embW, outW, Wh, Wo, Bre, Bim, Cre, Cim, gl);

    // embedding: h = half(x @ embW^T + embb)
    gemm_h<128,__half,1><<<dim3(HID/128, MB), tb, SM128>>>(M_TOT, HID, INDIM, xr, wE, embb, (const __half*)nullptr, h);

    for (int l = 0; l < NLAYERS; l++) {
        // bu = h @ Bcat^T   [M, 512] fp16 (gamma pre-applied)
        gemm_h<128,__half,0><<<dim3(S2/128, MB), tb, SM128>>>(M_TOT, S2, HID, h, wB + (size_t)l*S2*HID,
                                                              (const float*)nullptr, (const __half*)nullptr, bup);
        // fused chunked complex scan
        scan_fused<<<dim3(STATEN/16, BATCHN), 1024>>>(nu, th, l);

        // y = half([st interleaved] @ wC^T + D*h)
        gemm_h<128,__half,7><<<dim3(HID/128, MB), tb, SM128>>>(M_TOT, HID, S2, stp, wC + (size_t)l*HID*S2,
                                                               Dv + (size_t)l*HID, h, y);
        // MLP
        gemm_h<128,__half,2><<<dim3(MLPD/128, MB), tb, SM128>>>(M_TOT, MLPD, HID, y, wH + (size_t)l*MLPD*HID,
                                                                bh + (size_t)l*MLPD, (const __half*)nullptr, z);
        gemm_h<128,__half,3><<<dim3(HID/128, MB), tb, SM128>>>(M_TOT, HID, MLPD, z, wO + (size_t)l*HID*MLPD,
                                                               bo + (size_t)l*HID, y, h);
    }

    // out = h @ outW^T + outb   (fp32 store)
    gemm_h<128,float,1><<<dim3(OUTD/128, MB), tb, SM128>>>(M_TOT, OUTD, HID, h, wOut, outb, (const float*)nullptr, out);
}